// round 10
// baseline (speedup 1.0000x reference)
#include <cuda_runtime.h>
#include <math.h>

#define Bn 16
#define Cn 128
#define Ln 2048

#define PAD  136   // operands read as [kdim][x]
#define PADV 132   // operand read as [m][kdim]

// smem layout (floats)
#define QS_OFF 0
#define KS_OFF 17408            // 128*136
#define PS_OFF 34816
#define LM_OFF 52224            // 2048 log-mask
#define SR_OFF 54272            // 512 partial sums (4 wm x 128 q)
#define SI_OFF 54784            // 128 inv sums
#define SMEM_FLOATS 54912       // 219,648 bytes

__device__ float g_inv[Bn * Ln];   // per-query 1/rowsum, kernel1 -> kernel2

__device__ __forceinline__ unsigned f2tf32(float x) {
    unsigned r;
    asm("cvt.rna.tf32.f32 %0, %1;" : "=r"(r) : "f"(x));
    return r;
}

__device__ __forceinline__ void mma_tf32(float* c, const unsigned* a, const unsigned* b) {
    asm volatile(
        "mma.sync.aligned.m16n8k8.row.col.f32.tf32.tf32.f32 "
        "{%0,%1,%2,%3}, {%4,%5,%6,%7}, {%8,%9}, {%0,%1,%2,%3};"
        : "+f"(c[0]), "+f"(c[1]), "+f"(c[2]), "+f"(c[3])
        : "r"(a[0]), "r"(a[1]), "r"(a[2]), "r"(a[3]), "r"(b[0]), "r"(b[1]));
}

// ---------------------------------------------------------------------------
// Kernel 1: per (batch, 128-query strip): QK mma -> exp -> write unnormalized
// p to attT + row-sum accumulation; AV mma on the unnormalized P tile with
// final 1/sum scaling of the output accumulator. Single k-tile loop, K/V
// globals register-prefetched under the mma loops.
// 512 threads = 16 warps, warp grid 4(m) x 4(n), warp tile 32x32.
// ---------------------------------------------------------------------------
__global__ void __launch_bounds__(512, 1)
fused_attn_kernel(const float* __restrict__ Q, const float* __restrict__ Kg,
                  const float* __restrict__ V, const float* __restrict__ mask,
                  float* __restrict__ out, float* __restrict__ attT) {
    extern __shared__ float sm[];
    float* Qs   = sm + QS_OFF;   // [128 c][PAD]   tf32 Q tile (persistent)
    float* KVs  = sm + KS_OFF;   // [128][PAD/PADV] K tile then V tile
    float* Ps   = sm + PS_OFF;   // [128 k][PAD]   tf32 unnormalized P tile
    float* lm   = sm + LM_OFF;
    float* sred = sm + SR_OFF;
    float* sinv = sm + SI_OFF;

    const int b   = blockIdx.y;
    const int q0  = blockIdx.x * 128;
    const int tid = threadIdx.x;
    const int warp = tid >> 5, lane = tid & 31;
    const int wm = warp >> 2, wn = warp & 3;    // 4(m) x 4(n)
    const int g = lane >> 2, tg = lane & 3;

    const float* Qb = Q  + (size_t)b * Cn * Ln;
    const float* Kb = Kg + (size_t)b * Cn * Ln;
    const float* Vb = V  + (size_t)b * Cn * Ln;
    float* Tb = attT + (size_t)b * Ln * Ln;

    for (int i = tid; i < Ln; i += 512) lm[i] = __logf(mask[b * Ln + i] + 1e-6f);
    sred[tid] = 0.f;

    // stage Q tile [c][q] once (8 float4 / thread)
    const int srow = warp;           // staging row base (warp + i*16)
    const int scol = lane << 2;      // staging col (float4)
#pragma unroll
    for (int i = 0; i < 8; i++) {
        int r = srow + i * 16;
        float4 v = *reinterpret_cast<const float4*>(Qb + (size_t)r * Ln + q0 + scol);
        unsigned* d = reinterpret_cast<unsigned*>(Qs + r * PAD + scol);
        d[0] = f2tf32(v.x); d[1] = f2tf32(v.y); d[2] = f2tf32(v.z); d[3] = f2tf32(v.w);
    }

    // prefetch K tile 0
    float4 pf[8];
#pragma unroll
    for (int i = 0; i < 8; i++)
        pf[i] = *reinterpret_cast<const float4*>(Kb + (size_t)(srow + i * 16) * Ln + scol);

    __syncthreads();   // Q / lm / sred ready

    const float scale = 0.08838834764831845f;   // 1/sqrt(128)

    float oacc[2][4][4];
#pragma unroll
    for (int i = 0; i < 2; i++)
#pragma unroll
        for (int j = 0; j < 4; j++)
#pragma unroll
            for (int v = 0; v < 4; v++) oacc[i][j][v] = 0.f;

    for (int kt = 0; kt < 16; kt++) {
        const int k0 = kt * 128;

        // commit prefetched K tile to smem
#pragma unroll
        for (int i = 0; i < 8; i++) {
            unsigned* d = reinterpret_cast<unsigned*>(KVs + (srow + i * 16) * PAD + scol);
            d[0] = f2tf32(pf[i].x); d[1] = f2tf32(pf[i].y);
            d[2] = f2tf32(pf[i].z); d[3] = f2tf32(pf[i].w);
        }
        __syncthreads();                       // (1) K tile ready

        // prefetch V tile kt (lands during QK mma)
#pragma unroll
        for (int i = 0; i < 8; i++)
            pf[i] = *reinterpret_cast<const float4*>(Vb + (size_t)(srow + i * 16) * Ln + k0 + scol);

        // ---- QK mma: acc[m=krow 32][n=q 32] ----
        float acc[2][4][4];
#pragma unroll
        for (int i = 0; i < 2; i++)
#pragma unroll
            for (int j = 0; j < 4; j++)
#pragma unroll
                for (int v = 0; v < 4; v++) acc[i][j][v] = 0.f;

#pragma unroll
        for (int cc = 0; cc < Cn; cc += 8) {
            unsigned a[2][4];
#pragma unroll
            for (int mt = 0; mt < 2; mt++) {
                int m = wm * 32 + mt * 16 + g;
                a[mt][0] = __float_as_uint(KVs[(cc + tg) * PAD + m]);
                a[mt][1] = __float_as_uint(KVs[(cc + tg) * PAD + m + 8]);
                a[mt][2] = __float_as_uint(KVs[(cc + tg + 4) * PAD + m]);
                a[mt][3] = __float_as_uint(KVs[(cc + tg + 4) * PAD + m + 8]);
            }
#pragma unroll
            for (int nt = 0; nt < 4; nt++) {
                int n = wn * 32 + nt * 8 + g;
                unsigned bb[2];
                bb[0] = __float_as_uint(Qs[(cc + tg) * PAD + n]);
                bb[1] = __float_as_uint(Qs[(cc + tg + 4) * PAD + n]);
                mma_tf32(acc[0][nt], a[0], bb);
                mma_tf32(acc[1][nt], a[1], bb);
            }
        }

        // ---- epilogue: p = exp(scale*e + logmask); store p; stash tf32 ----
        float sp[8];
#pragma unroll
        for (int j = 0; j < 8; j++) sp[j] = 0.f;
#pragma unroll
        for (int mt = 0; mt < 2; mt++) {
            int krl = wm * 32 + mt * 16 + g;
            int kgl = k0 + krl;
            float l0 = lm[kgl], l1 = lm[kgl + 8];
            float* row0 = Tb + (size_t)kgl * Ln + q0 + wn * 32;
            float* row1 = row0 + (size_t)8 * Ln;
#pragma unroll
            for (int nt = 0; nt < 4; nt++) {
                int qoff = nt * 8 + 2 * tg;
                float p0 = __expf(fmaf(acc[mt][nt][0], scale, l0));
                float p1 = __expf(fmaf(acc[mt][nt][1], scale, l0));
                float p2 = __expf(fmaf(acc[mt][nt][2], scale, l1));
                float p3 = __expf(fmaf(acc[mt][nt][3], scale, l1));
                sp[nt * 2]     += p0 + p2;
                sp[nt * 2 + 1] += p1 + p3;
                __stcs(reinterpret_cast<float2*>(row0 + qoff), make_float2(p0, p1));
                __stcs(reinterpret_cast<float2*>(row1 + qoff), make_float2(p2, p3));
                float2 t0 = make_float2(__uint_as_float(f2tf32(p0)),
                                        __uint_as_float(f2tf32(p1)));
                float2 t1 = make_float2(__uint_as_float(f2tf32(p2)),
                                        __uint_as_float(f2tf32(p3)));
                *reinterpret_cast<float2*>(Ps + krl * PAD + wn * 32 + qoff)       = t0;
                *reinterpret_cast<float2*>(Ps + (krl + 8) * PAD + wn * 32 + qoff) = t1;
            }
        }
        // fold partial sums (reduce over g lanes, accumulate in smem)
#pragma unroll
        for (int j = 0; j < 8; j++) {
            float v = sp[j];
            v += __shfl_xor_sync(0xffffffffu, v, 4);
            v += __shfl_xor_sync(0xffffffffu, v, 8);
            v += __shfl_xor_sync(0xffffffffu, v, 16);
            if (g == 0)
                sred[wm * 128 + wn * 32 + (j >> 1) * 8 + 2 * tg + (j & 1)] += v;
        }
        __syncthreads();                       // (2) Ps done, K reads done

        // commit prefetched V tile (overwrites K buffer, PADV layout)
#pragma unroll
        for (int i = 0; i < 8; i++) {
            unsigned* d = reinterpret_cast<unsigned*>(KVs + (srow + i * 16) * PADV + scol);
            d[0] = f2tf32(pf[i].x); d[1] = f2tf32(pf[i].y);
            d[2] = f2tf32(pf[i].z); d[3] = f2tf32(pf[i].w);
        }
        __syncthreads();                       // (3) V tile ready

        // prefetch K tile kt+1 (lands during AV mma)
        {
            int kn0 = ((kt + 1) & 15) * 128;
#pragma unroll
            for (int i = 0; i < 8; i++)
                pf[i] = *reinterpret_cast<const float4*>(Vb == NULL ? NULL :
                        Kb + (size_t)(srow + i * 16) * Ln + kn0 + scol);
        }

        // ---- AV mma: oacc[m=c 32][n=q 32] += V * P ----
#pragma unroll
        for (int kk = 0; kk < 128; kk += 8) {
            unsigned a[2][4];
#pragma unroll
            for (int mt = 0; mt < 2; mt++) {
                int m = wm * 32 + mt * 16 + g;
                a[mt][0] = __float_as_uint(KVs[m * PADV + kk + tg]);
                a[mt][1] = __float_as_uint(KVs[(m + 8) * PADV + kk + tg]);
                a[mt][2] = __float_as_uint(KVs[m * PADV + kk + tg + 4]);
                a[mt][3] = __float_as_uint(KVs[(m + 8) * PADV + kk + tg + 4]);
            }
#pragma unroll
            for (int nt = 0; nt < 4; nt++) {
                int n = wn * 32 + nt * 8 + g;
                unsigned bb[2];
                bb[0] = __float_as_uint(Ps[(kk + tg) * PAD + n]);
                bb[1] = __float_as_uint(Ps[(kk + tg + 4) * PAD + n]);
                mma_tf32(oacc[0][nt], a[0], bb);
                mma_tf32(oacc[1][nt], a[1], bb);
            }
        }
        __syncthreads();                       // (4) V/P reads done
    }

    // per-query inverse sums
    if (tid < 128) {
        float s = sred[tid] + sred[128 + tid] + sred[256 + tid] + sred[384 + tid];
        float iv = 1.0f / s;
        sinv[tid] = iv;
        g_inv[b * Ln + q0 + tid] = iv;
    }
    __syncthreads();

    // out[b][c][q] = oacc * inv[q]
    float* ob = out + (size_t)b * Cn * Ln;
#pragma unroll
    for (int mt = 0; mt < 2; mt++) {
        int c = wm * 32 + mt * 16 + g;
#pragma unroll
        for (int nt = 0; nt < 4; nt++) {
            int qloc = wn * 32 + nt * 8 + 2 * tg;
            float i0 = sinv[qloc], i1 = sinv[qloc + 1];
            __stcs(reinterpret_cast<float2*>(ob + (size_t)c * Ln + q0 + qloc),
                   make_float2(oacc[mt][nt][0] * i0, oacc[mt][nt][1] * i1));
            __stcs(reinterpret_cast<float2*>(ob + (size_t)(c + 8) * Ln + q0 + qloc),
                   make_float2(oacc[mt][nt][2] * i0, oacc[mt][nt][3] * i1));
        }
    }
}

// ---------------------------------------------------------------------------
// Kernel 2: attT[b][k][q] *= g_inv[b][q] * mask[b][k]   (in place, streaming)
// One block per (b, k-row): 512 threads x float4 = 2048 floats.
// Masked rows skip the read and store zeros.
// ---------------------------------------------------------------------------
__global__ void __launch_bounds__(512)
normalize_kernel(const float* __restrict__ mask, float* __restrict__ attT) {
    const int k = blockIdx.x;
    const int b = blockIdx.y;
    const int tid = threadIdx.x;
    float* p = attT + ((size_t)b * Ln + k) * Ln + tid * 4;
    float mk = __ldg(mask + b * Ln + k);
    if (mk == 0.0f) {
        __stcs(reinterpret_cast<float4*>(p), make_float4(0.f, 0.f, 0.f, 0.f));
        return;
    }
    float4 iv = *reinterpret_cast<const float4*>(g_inv + b * Ln + tid * 4);
    float4 v = *reinterpret_cast<const float4*>(p);
    v.x *= iv.x; v.y *= iv.y; v.z *= iv.z; v.w *= iv.w;
    __stcs(reinterpret_cast<float4*>(p), v);
}

// ---------------------------------------------------------------------------
extern "C" void kernel_launch(void* const* d_in, const int* in_sizes, int n_in,
                              void* d_out, int out_size) {
    const float* Q    = (const float*)d_in[0];
    const float* K    = (const float*)d_in[1];
    const float* V    = (const float*)d_in[2];
    const float* mask = (const float*)d_in[3];

    float* out  = (float*)d_out;                  // [B, C, L]
    float* attT = out + (size_t)Bn * Cn * Ln;     // [B, Lk, Lq]

    const int SMEM = SMEM_FLOATS * 4;             // 219,648 B
    cudaFuncSetAttribute(fused_attn_kernel,
                         cudaFuncAttributeMaxDynamicSharedMemorySize, SMEM);

    dim3 g1(Ln / 128, Bn);                        // (16, 16) = 256 blocks
    fused_attn_kernel<<<g1, 512, SMEM>>>(Q, K, V, mask, out, attT);

    dim3 g2(Ln, Bn);                              // (2048, 16)
    normalize_kernel<<<g2, 512>>>(mask, attT);
}

// round 11
// speedup vs baseline: 1.0019x; 1.0019x over previous
#include <cuda_runtime.h>
#include <math.h>

#define Bn 16
#define Cn 128
#define Ln 2048

#define PAD  136   // operands read as [kdim][x]
#define PADV 132   // operand read as [m][kdim]

// smem layout (floats)
#define QS_OFF 0
#define KS_OFF 17408            // 128*136
#define PS_OFF 34816
#define LM_OFF 52224            // 2048 log-mask
#define SR_OFF 54272            // 512 partial sums (4 wm x 128 q)
#define SI_OFF 54784            // 128 inv sums
#define SMEM_FLOATS 54912       // 219,648 bytes

__device__ float g_inv[Bn * Ln];   // per-query 1/rowsum, kernel1 -> kernel2

__device__ __forceinline__ unsigned f2tf32(float x) {
    unsigned r;
    asm("cvt.rna.tf32.f32 %0, %1;" : "=r"(r) : "f"(x));
    return r;
}

__device__ __forceinline__ void mma_tf32(float* c, const unsigned* a, const unsigned* b) {
    asm volatile(
        "mma.sync.aligned.m16n8k8.row.col.f32.tf32.tf32.f32 "
        "{%0,%1,%2,%3}, {%4,%5,%6,%7}, {%8,%9}, {%0,%1,%2,%3};"
        : "+f"(c[0]), "+f"(c[1]), "+f"(c[2]), "+f"(c[3])
        : "r"(a[0]), "r"(a[1]), "r"(a[2]), "r"(a[3]), "r"(b[0]), "r"(b[1]));
}

// ---------------------------------------------------------------------------
// Kernel 1: per (batch, 128-query strip): QK mma -> exp -> write unnormalized
// p to attT + row-sum accumulation; AV mma on the unnormalized P tile with
// final 1/sum scaling of the output accumulator. Single k-tile loop, K/V
// globals register-prefetched under the mma loops.
// 512 threads = 16 warps, warp grid 4(m) x 4(n), warp tile 32x32.
// ---------------------------------------------------------------------------
__global__ void __launch_bounds__(512, 1)
fused_attn_kernel(const float* __restrict__ Q, const float* __restrict__ Kg,
                  const float* __restrict__ V, const float* __restrict__ mask,
                  float* __restrict__ out, float* __restrict__ attT) {
    extern __shared__ float sm[];
    float* Qs   = sm + QS_OFF;   // [128 c][PAD]   tf32 Q tile (persistent)
    float* KVs  = sm + KS_OFF;   // [128][PAD/PADV] K tile then V tile
    float* Ps   = sm + PS_OFF;   // [128 k][PAD]   tf32 unnormalized P tile
    float* lm   = sm + LM_OFF;
    float* sred = sm + SR_OFF;
    float* sinv = sm + SI_OFF;

    const int b   = blockIdx.y;
    const int q0  = blockIdx.x * 128;
    const int tid = threadIdx.x;
    const int warp = tid >> 5, lane = tid & 31;
    const int wm = warp >> 2, wn = warp & 3;    // 4(m) x 4(n)
    const int g = lane >> 2, tg = lane & 3;

    const float* Qb = Q  + (size_t)b * Cn * Ln;
    const float* Kb = Kg + (size_t)b * Cn * Ln;
    const float* Vb = V  + (size_t)b * Cn * Ln;
    float* Tb = attT + (size_t)b * Ln * Ln;

    for (int i = tid; i < Ln; i += 512) lm[i] = __logf(mask[b * Ln + i] + 1e-6f);
    sred[tid] = 0.f;

    // stage Q tile [c][q] once (8 float4 / thread)
    const int srow = warp;           // staging row base (warp + i*16)
    const int scol = lane << 2;      // staging col (float4)
#pragma unroll
    for (int i = 0; i < 8; i++) {
        int r = srow + i * 16;
        float4 v = *reinterpret_cast<const float4*>(Qb + (size_t)r * Ln + q0 + scol);
        unsigned* d = reinterpret_cast<unsigned*>(Qs + r * PAD + scol);
        d[0] = f2tf32(v.x); d[1] = f2tf32(v.y); d[2] = f2tf32(v.z); d[3] = f2tf32(v.w);
    }

    // prefetch K tile 0
    float4 pf[8];
#pragma unroll
    for (int i = 0; i < 8; i++)
        pf[i] = *reinterpret_cast<const float4*>(Kb + (size_t)(srow + i * 16) * Ln + scol);

    __syncthreads();   // Q / lm / sred ready

    const float scale = 0.08838834764831845f;   // 1/sqrt(128)

    float oacc[2][4][4];
#pragma unroll
    for (int i = 0; i < 2; i++)
#pragma unroll
        for (int j = 0; j < 4; j++)
#pragma unroll
            for (int v = 0; v < 4; v++) oacc[i][j][v] = 0.f;

    for (int kt = 0; kt < 16; kt++) {
        const int k0 = kt * 128;

        // commit prefetched K tile to smem
#pragma unroll
        for (int i = 0; i < 8; i++) {
            unsigned* d = reinterpret_cast<unsigned*>(KVs + (srow + i * 16) * PAD + scol);
            d[0] = f2tf32(pf[i].x); d[1] = f2tf32(pf[i].y);
            d[2] = f2tf32(pf[i].z); d[3] = f2tf32(pf[i].w);
        }
        __syncthreads();                       // (1) K tile ready

        // prefetch V tile kt (lands during QK mma)
#pragma unroll
        for (int i = 0; i < 8; i++)
            pf[i] = *reinterpret_cast<const float4*>(Vb + (size_t)(srow + i * 16) * Ln + k0 + scol);

        // ---- QK mma: acc[m=krow 32][n=q 32] ----
        float acc[2][4][4];
#pragma unroll
        for (int i = 0; i < 2; i++)
#pragma unroll
            for (int j = 0; j < 4; j++)
#pragma unroll
                for (int v = 0; v < 4; v++) acc[i][j][v] = 0.f;

#pragma unroll
        for (int cc = 0; cc < Cn; cc += 8) {
            unsigned a[2][4];
#pragma unroll
            for (int mt = 0; mt < 2; mt++) {
                int m = wm * 32 + mt * 16 + g;
                a[mt][0] = __float_as_uint(KVs[(cc + tg) * PAD + m]);
                a[mt][1] = __float_as_uint(KVs[(cc + tg) * PAD + m + 8]);
                a[mt][2] = __float_as_uint(KVs[(cc + tg + 4) * PAD + m]);
                a[mt][3] = __float_as_uint(KVs[(cc + tg + 4) * PAD + m + 8]);
            }
#pragma unroll
            for (int nt = 0; nt < 4; nt++) {
                int n = wn * 32 + nt * 8 + g;
                unsigned bb[2];
                bb[0] = __float_as_uint(Qs[(cc + tg) * PAD + n]);
                bb[1] = __float_as_uint(Qs[(cc + tg + 4) * PAD + n]);
                mma_tf32(acc[0][nt], a[0], bb);
                mma_tf32(acc[1][nt], a[1], bb);
            }
        }

        // ---- epilogue: p = exp(scale*e + logmask); store p; stash tf32 ----
        float sp[8];
#pragma unroll
        for (int j = 0; j < 8; j++) sp[j] = 0.f;
#pragma unroll
        for (int mt = 0; mt < 2; mt++) {
            int krl = wm * 32 + mt * 16 + g;
            int kgl = k0 + krl;
            float l0 = lm[kgl], l1 = lm[kgl + 8];
            float* row0 = Tb + (size_t)kgl * Ln + q0 + wn * 32;
            float* row1 = row0 + (size_t)8 * Ln;
#pragma unroll
            for (int nt = 0; nt < 4; nt++) {
                int qoff = nt * 8 + 2 * tg;
                float p0 = __expf(fmaf(acc[mt][nt][0], scale, l0));
                float p1 = __expf(fmaf(acc[mt][nt][1], scale, l0));
                float p2 = __expf(fmaf(acc[mt][nt][2], scale, l1));
                float p3 = __expf(fmaf(acc[mt][nt][3], scale, l1));
                sp[nt * 2]     += p0 + p2;
                sp[nt * 2 + 1] += p1 + p3;
                __stcs(reinterpret_cast<float2*>(row0 + qoff), make_float2(p0, p1));
                __stcs(reinterpret_cast<float2*>(row1 + qoff), make_float2(p2, p3));
                float2 t0 = make_float2(__uint_as_float(f2tf32(p0)),
                                        __uint_as_float(f2tf32(p1)));
                float2 t1 = make_float2(__uint_as_float(f2tf32(p2)),
                                        __uint_as_float(f2tf32(p3)));
                *reinterpret_cast<float2*>(Ps + krl * PAD + wn * 32 + qoff)       = t0;
                *reinterpret_cast<float2*>(Ps + (krl + 8) * PAD + wn * 32 + qoff) = t1;
            }
        }
        // fold partial sums (reduce over g lanes, accumulate in smem)
#pragma unroll
        for (int j = 0; j < 8; j++) {
            float v = sp[j];
            v += __shfl_xor_sync(0xffffffffu, v, 4);
            v += __shfl_xor_sync(0xffffffffu, v, 8);
            v += __shfl_xor_sync(0xffffffffu, v, 16);
            if (g == 0)
                sred[wm * 128 + wn * 32 + (j >> 1) * 8 + 2 * tg + (j & 1)] += v;
        }
        __syncthreads();                       // (2) Ps done, K reads done

        // commit prefetched V tile (overwrites K buffer, PADV layout)
#pragma unroll
        for (int i = 0; i < 8; i++) {
            unsigned* d = reinterpret_cast<unsigned*>(KVs + (srow + i * 16) * PADV + scol);
            d[0] = f2tf32(pf[i].x); d[1] = f2tf32(pf[i].y);
            d[2] = f2tf32(pf[i].z); d[3] = f2tf32(pf[i].w);
        }
        __syncthreads();                       // (3) V tile ready

        // prefetch K tile kt+1 (lands during AV mma)
        {
            int kn0 = ((kt + 1) & 15) * 128;
#pragma unroll
            for (int i = 0; i < 8; i++)
                pf[i] = *reinterpret_cast<const float4*>(Vb == NULL ? NULL :
                        Kb + (size_t)(srow + i * 16) * Ln + kn0 + scol);
        }

        // ---- AV mma: oacc[m=c 32][n=q 32] += V * P ----
#pragma unroll
        for (int kk = 0; kk < 128; kk += 8) {
            unsigned a[2][4];
#pragma unroll
            for (int mt = 0; mt < 2; mt++) {
                int m = wm * 32 + mt * 16 + g;
                a[mt][0] = __float_as_uint(KVs[m * PADV + kk + tg]);
                a[mt][1] = __float_as_uint(KVs[(m + 8) * PADV + kk + tg]);
                a[mt][2] = __float_as_uint(KVs[m * PADV + kk + tg + 4]);
                a[mt][3] = __float_as_uint(KVs[(m + 8) * PADV + kk + tg + 4]);
            }
#pragma unroll
            for (int nt = 0; nt < 4; nt++) {
                int n = wn * 32 + nt * 8 + g;
                unsigned bb[2];
                bb[0] = __float_as_uint(Ps[(kk + tg) * PAD + n]);
                bb[1] = __float_as_uint(Ps[(kk + tg + 4) * PAD + n]);
                mma_tf32(oacc[0][nt], a[0], bb);
                mma_tf32(oacc[1][nt], a[1], bb);
            }
        }
        __syncthreads();                       // (4) V/P reads done
    }

    // per-query inverse sums
    if (tid < 128) {
        float s = sred[tid] + sred[128 + tid] + sred[256 + tid] + sred[384 + tid];
        float iv = 1.0f / s;
        sinv[tid] = iv;
        g_inv[b * Ln + q0 + tid] = iv;
    }
    __syncthreads();

    // out[b][c][q] = oacc * inv[q]
    float* ob = out + (size_t)b * Cn * Ln;
#pragma unroll
    for (int mt = 0; mt < 2; mt++) {
        int c = wm * 32 + mt * 16 + g;
#pragma unroll
        for (int nt = 0; nt < 4; nt++) {
            int qloc = wn * 32 + nt * 8 + 2 * tg;
            float i0 = sinv[qloc], i1 = sinv[qloc + 1];
            __stcs(reinterpret_cast<float2*>(ob + (size_t)c * Ln + q0 + qloc),
                   make_float2(oacc[mt][nt][0] * i0, oacc[mt][nt][1] * i1));
            __stcs(reinterpret_cast<float2*>(ob + (size_t)(c + 8) * Ln + q0 + qloc),
                   make_float2(oacc[mt][nt][2] * i0, oacc[mt][nt][3] * i1));
        }
    }
}

// ---------------------------------------------------------------------------
// Kernel 2: attT[b][k][q] *= g_inv[b][q] * mask[b][k]   (in place, streaming)
// One block per (b, k-row): 512 threads x float4 = 2048 floats.
// Masked rows skip the read and store zeros.
// ---------------------------------------------------------------------------
__global__ void __launch_bounds__(512)
normalize_kernel(const float* __restrict__ mask, float* __restrict__ attT) {
    const int k = blockIdx.x;
    const int b = blockIdx.y;
    const int tid = threadIdx.x;
    float* p = attT + ((size_t)b * Ln + k) * Ln + tid * 4;
    float mk = __ldg(mask + b * Ln + k);
    if (mk == 0.0f) {
        __stcs(reinterpret_cast<float4*>(p), make_float4(0.f, 0.f, 0.f, 0.f));
        return;
    }
    float4 iv = *reinterpret_cast<const float4*>(g_inv + b * Ln + tid * 4);
    float4 v = *reinterpret_cast<const float4*>(p);
    v.x *= iv.x; v.y *= iv.y; v.z *= iv.z; v.w *= iv.w;
    __stcs(reinterpret_cast<float4*>(p), v);
}

// ---------------------------------------------------------------------------
extern "C" void kernel_launch(void* const* d_in, const int* in_sizes, int n_in,
                              void* d_out, int out_size) {
    const float* Q    = (const float*)d_in[0];
    const float* K    = (const float*)d_in[1];
    const float* V    = (const float*)d_in[2];
    const float* mask = (const float*)d_in[3];

    float* out  = (float*)d_out;                  // [B, C, L]
    float* attT = out + (size_t)Bn * Cn * Ln;     // [B, Lk, Lq]

    const int SMEM = SMEM_FLOATS * 4;             // 219,648 B
    cudaFuncSetAttribute(fused_attn_kernel,
                         cudaFuncAttributeMaxDynamicSharedMemorySize, SMEM);

    dim3 g1(Ln / 128, Bn);                        // (16, 16) = 256 blocks
    fused_attn_kernel<<<g1, 512, SMEM>>>(Q, K, V, mask, out, attT);

    dim3 g2(Ln, Bn);                              // (2048, 16)
    normalize_kernel<<<g2, 512>>>(mask, attT);
}

// round 12
// speedup vs baseline: 1.0054x; 1.0035x over previous
#include <cuda_runtime.h>
#include <math.h>

#define Bn 16
#define Cn 128
#define Ln 2048

#define PAD  136   // operands read as [kdim][x]
#define PADV 132   // operand read as [m][kdim]

// smem layout (floats)
#define QS_OFF 0
#define KS_OFF 17408            // 128*136
#define PS_OFF 34816
#define LM_OFF 52224            // 2048 log-mask
#define SR_OFF 54272            // 512 partial sums (4 wm x 128 q)
#define SI_OFF 54784            // 128 inv sums
#define SMEM_FLOATS 54912       // 219,648 bytes

__device__ float g_inv[Bn * Ln];   // per-query 1/rowsum, kernel1 -> kernel2

__device__ __forceinline__ unsigned f2tf32(float x) {
    unsigned r;
    asm("cvt.rna.tf32.f32 %0, %1;" : "=r"(r) : "f"(x));
    return r;
}

__device__ __forceinline__ void mma_tf32(float* c, const unsigned* a, const unsigned* b) {
    asm volatile(
        "mma.sync.aligned.m16n8k8.row.col.f32.tf32.tf32.f32 "
        "{%0,%1,%2,%3}, {%4,%5,%6,%7}, {%8,%9}, {%0,%1,%2,%3};"
        : "+f"(c[0]), "+f"(c[1]), "+f"(c[2]), "+f"(c[3])
        : "r"(a[0]), "r"(a[1]), "r"(a[2]), "r"(a[3]), "r"(b[0]), "r"(b[1]));
}

// ---------------------------------------------------------------------------
// Kernel 1: per (batch, 128-query strip): QK mma -> exp -> write unnormalized
// p to attT + row-sum accumulation; AV mma on the unnormalized P tile with
// final 1/sum scaling of the output accumulator. Single k-tile loop, K/V
// globals register-prefetched under the mma loops.
// 512 threads = 16 warps, warp grid 4(m) x 4(n), warp tile 32x32.
// ---------------------------------------------------------------------------
__global__ void __launch_bounds__(512, 1)
fused_attn_kernel(const float* __restrict__ Q, const float* __restrict__ Kg,
                  const float* __restrict__ V, const float* __restrict__ mask,
                  float* __restrict__ out, float* __restrict__ attT) {
    extern __shared__ float sm[];
    float* Qs   = sm + QS_OFF;   // [128 c][PAD]   tf32 Q tile (persistent)
    float* KVs  = sm + KS_OFF;   // [128][PAD/PADV] K tile then V tile
    float* Ps   = sm + PS_OFF;   // [128 k][PAD]   tf32 unnormalized P tile
    float* lm   = sm + LM_OFF;
    float* sred = sm + SR_OFF;
    float* sinv = sm + SI_OFF;

    const int b   = blockIdx.y;
    const int q0  = blockIdx.x * 128;
    const int tid = threadIdx.x;
    const int warp = tid >> 5, lane = tid & 31;
    const int wm = warp >> 2, wn = warp & 3;    // 4(m) x 4(n)
    const int g = lane >> 2, tg = lane & 3;

    const float* Qb = Q  + (size_t)b * Cn * Ln;
    const float* Kb = Kg + (size_t)b * Cn * Ln;
    const float* Vb = V  + (size_t)b * Cn * Ln;
    float* Tb = attT + (size_t)b * Ln * Ln;

    for (int i = tid; i < Ln; i += 512) lm[i] = __logf(mask[b * Ln + i] + 1e-6f);
    sred[tid] = 0.f;

    // stage Q tile [c][q] once (8 float4 / thread)
    const int srow = warp;           // staging row base (warp + i*16)
    const int scol = lane << 2;      // staging col (float4)
#pragma unroll
    for (int i = 0; i < 8; i++) {
        int r = srow + i * 16;
        float4 v = *reinterpret_cast<const float4*>(Qb + (size_t)r * Ln + q0 + scol);
        unsigned* d = reinterpret_cast<unsigned*>(Qs + r * PAD + scol);
        d[0] = f2tf32(v.x); d[1] = f2tf32(v.y); d[2] = f2tf32(v.z); d[3] = f2tf32(v.w);
    }

    // prefetch K tile 0
    float4 pf[8];
#pragma unroll
    for (int i = 0; i < 8; i++)
        pf[i] = *reinterpret_cast<const float4*>(Kb + (size_t)(srow + i * 16) * Ln + scol);

    __syncthreads();   // Q / lm / sred ready

    const float scale = 0.08838834764831845f;   // 1/sqrt(128)

    float oacc[2][4][4];
#pragma unroll
    for (int i = 0; i < 2; i++)
#pragma unroll
        for (int j = 0; j < 4; j++)
#pragma unroll
            for (int v = 0; v < 4; v++) oacc[i][j][v] = 0.f;

    for (int kt = 0; kt < 16; kt++) {
        const int k0 = kt * 128;

        // commit prefetched K tile to smem
#pragma unroll
        for (int i = 0; i < 8; i++) {
            unsigned* d = reinterpret_cast<unsigned*>(KVs + (srow + i * 16) * PAD + scol);
            d[0] = f2tf32(pf[i].x); d[1] = f2tf32(pf[i].y);
            d[2] = f2tf32(pf[i].z); d[3] = f2tf32(pf[i].w);
        }
        __syncthreads();                       // (1) K tile ready

        // prefetch V tile kt (lands during QK mma)
#pragma unroll
        for (int i = 0; i < 8; i++)
            pf[i] = *reinterpret_cast<const float4*>(Vb + (size_t)(srow + i * 16) * Ln + k0 + scol);

        // ---- QK mma: acc[m=krow 32][n=q 32] ----
        float acc[2][4][4];
#pragma unroll
        for (int i = 0; i < 2; i++)
#pragma unroll
            for (int j = 0; j < 4; j++)
#pragma unroll
                for (int v = 0; v < 4; v++) acc[i][j][v] = 0.f;

#pragma unroll
        for (int cc = 0; cc < Cn; cc += 8) {
            unsigned a[2][4];
#pragma unroll
            for (int mt = 0; mt < 2; mt++) {
                int m = wm * 32 + mt * 16 + g;
                a[mt][0] = __float_as_uint(KVs[(cc + tg) * PAD + m]);
                a[mt][1] = __float_as_uint(KVs[(cc + tg) * PAD + m + 8]);
                a[mt][2] = __float_as_uint(KVs[(cc + tg + 4) * PAD + m]);
                a[mt][3] = __float_as_uint(KVs[(cc + tg + 4) * PAD + m + 8]);
            }
#pragma unroll
            for (int nt = 0; nt < 4; nt++) {
                int n = wn * 32 + nt * 8 + g;
                unsigned bb[2];
                bb[0] = __float_as_uint(Qs[(cc + tg) * PAD + n]);
                bb[1] = __float_as_uint(Qs[(cc + tg + 4) * PAD + n]);
                mma_tf32(acc[0][nt], a[0], bb);
                mma_tf32(acc[1][nt], a[1], bb);
            }
        }

        // ---- epilogue: p = exp(scale*e + logmask); store p; stash tf32 ----
        float sp[8];
#pragma unroll
        for (int j = 0; j < 8; j++) sp[j] = 0.f;
#pragma unroll
        for (int mt = 0; mt < 2; mt++) {
            int krl = wm * 32 + mt * 16 + g;
            int kgl = k0 + krl;
            float l0 = lm[kgl], l1 = lm[kgl + 8];
            float* row0 = Tb + (size_t)kgl * Ln + q0 + wn * 32;
            float* row1 = row0 + (size_t)8 * Ln;
#pragma unroll
            for (int nt = 0; nt < 4; nt++) {
                int qoff = nt * 8 + 2 * tg;
                float p0 = __expf(fmaf(acc[mt][nt][0], scale, l0));
                float p1 = __expf(fmaf(acc[mt][nt][1], scale, l0));
                float p2 = __expf(fmaf(acc[mt][nt][2], scale, l1));
                float p3 = __expf(fmaf(acc[mt][nt][3], scale, l1));
                sp[nt * 2]     += p0 + p2;
                sp[nt * 2 + 1] += p1 + p3;
                __stcs(reinterpret_cast<float2*>(row0 + qoff), make_float2(p0, p1));
                __stcs(reinterpret_cast<float2*>(row1 + qoff), make_float2(p2, p3));
                float2 t0 = make_float2(__uint_as_float(f2tf32(p0)),
                                        __uint_as_float(f2tf32(p1)));
                float2 t1 = make_float2(__uint_as_float(f2tf32(p2)),
                                        __uint_as_float(f2tf32(p3)));
                *reinterpret_cast<float2*>(Ps + krl * PAD + wn * 32 + qoff)       = t0;
                *reinterpret_cast<float2*>(Ps + (krl + 8) * PAD + wn * 32 + qoff) = t1;
            }
        }
        // fold partial sums (reduce over g lanes, accumulate in smem)
#pragma unroll
        for (int j = 0; j < 8; j++) {
            float v = sp[j];
            v += __shfl_xor_sync(0xffffffffu, v, 4);
            v += __shfl_xor_sync(0xffffffffu, v, 8);
            v += __shfl_xor_sync(0xffffffffu, v, 16);
            if (g == 0)
                sred[wm * 128 + wn * 32 + (j >> 1) * 8 + 2 * tg + (j & 1)] += v;
        }
        __syncthreads();                       // (2) Ps done, K reads done

        // commit prefetched V tile (overwrites K buffer, PADV layout)
#pragma unroll
        for (int i = 0; i < 8; i++) {
            unsigned* d = reinterpret_cast<unsigned*>(KVs + (srow + i * 16) * PADV + scol);
            d[0] = f2tf32(pf[i].x); d[1] = f2tf32(pf[i].y);
            d[2] = f2tf32(pf[i].z); d[3] = f2tf32(pf[i].w);
        }
        __syncthreads();                       // (3) V tile ready

        // prefetch K tile kt+1 (lands during AV mma)
        {
            int kn0 = ((kt + 1) & 15) * 128;
#pragma unroll
            for (int i = 0; i < 8; i++)
                pf[i] = *reinterpret_cast<const float4*>(Vb == NULL ? NULL :
                        Kb + (size_t)(srow + i * 16) * Ln + kn0 + scol);
        }

        // ---- AV mma: oacc[m=c 32][n=q 32] += V * P ----
#pragma unroll
        for (int kk = 0; kk < 128; kk += 8) {
            unsigned a[2][4];
#pragma unroll
            for (int mt = 0; mt < 2; mt++) {
                int m = wm * 32 + mt * 16 + g;
                a[mt][0] = __float_as_uint(KVs[m * PADV + kk + tg]);
                a[mt][1] = __float_as_uint(KVs[(m + 8) * PADV + kk + tg]);
                a[mt][2] = __float_as_uint(KVs[m * PADV + kk + tg + 4]);
                a[mt][3] = __float_as_uint(KVs[(m + 8) * PADV + kk + tg + 4]);
            }
#pragma unroll
            for (int nt = 0; nt < 4; nt++) {
                int n = wn * 32 + nt * 8 + g;
                unsigned bb[2];
                bb[0] = __float_as_uint(Ps[(kk + tg) * PAD + n]);
                bb[1] = __float_as_uint(Ps[(kk + tg + 4) * PAD + n]);
                mma_tf32(oacc[0][nt], a[0], bb);
                mma_tf32(oacc[1][nt], a[1], bb);
            }
        }
        __syncthreads();                       // (4) V/P reads done
    }

    // per-query inverse sums
    if (tid < 128) {
        float s = sred[tid] + sred[128 + tid] + sred[256 + tid] + sred[384 + tid];
        float iv = 1.0f / s;
        sinv[tid] = iv;
        g_inv[b * Ln + q0 + tid] = iv;
    }
    __syncthreads();

    // out[b][c][q] = oacc * inv[q]
    float* ob = out + (size_t)b * Cn * Ln;
#pragma unroll
    for (int mt = 0; mt < 2; mt++) {
        int c = wm * 32 + mt * 16 + g;
#pragma unroll
        for (int nt = 0; nt < 4; nt++) {
            int qloc = wn * 32 + nt * 8 + 2 * tg;
            float i0 = sinv[qloc], i1 = sinv[qloc + 1];
            __stcs(reinterpret_cast<float2*>(ob + (size_t)c * Ln + q0 + qloc),
                   make_float2(oacc[mt][nt][0] * i0, oacc[mt][nt][1] * i1));
            __stcs(reinterpret_cast<float2*>(ob + (size_t)(c + 8) * Ln + q0 + qloc),
                   make_float2(oacc[mt][nt][2] * i0, oacc[mt][nt][3] * i1));
        }
    }
}

// ---------------------------------------------------------------------------
// Kernel 2: attT[b][k][q] *= g_inv[b][q] * mask[b][k]   (in place, streaming)
// One block per (b, k-row): 512 threads x float4 = 2048 floats.
// Masked rows skip the read and store zeros.
// ---------------------------------------------------------------------------
__global__ void __launch_bounds__(512)
normalize_kernel(const float* __restrict__ mask, float* __restrict__ attT) {
    const int k = blockIdx.x;
    const int b = blockIdx.y;
    const int tid = threadIdx.x;
    float* p = attT + ((size_t)b * Ln + k) * Ln + tid * 4;
    float mk = __ldg(mask + b * Ln + k);
    if (mk == 0.0f) {
        __stcs(reinterpret_cast<float4*>(p), make_float4(0.f, 0.f, 0.f, 0.f));
        return;
    }
    float4 iv = *reinterpret_cast<const float4*>(g_inv + b * Ln + tid * 4);
    float4 v = *reinterpret_cast<const float4*>(p);
    v.x *= iv.x; v.y *= iv.y; v.z *= iv.z; v.w *= iv.w;
    __stcs(reinterpret_cast<float4*>(p), v);
}

// ---------------------------------------------------------------------------
extern "C" void kernel_launch(void* const* d_in, const int* in_sizes, int n_in,
                              void* d_out, int out_size) {
    const float* Q    = (const float*)d_in[0];
    const float* K    = (const float*)d_in[1];
    const float* V    = (const float*)d_in[2];
    const float* mask = (const float*)d_in[3];

    float* out  = (float*)d_out;                  // [B, C, L]
    float* attT = out + (size_t)Bn * Cn * Ln;     // [B, Lk, Lq]

    const int SMEM = SMEM_FLOATS * 4;             // 219,648 B
    cudaFuncSetAttribute(fused_attn_kernel,
                         cudaFuncAttributeMaxDynamicSharedMemorySize, SMEM);

    dim3 g1(Ln / 128, Bn);                        // (16, 16) = 256 blocks
    fused_attn_kernel<<<g1, 512, SMEM>>>(Q, K, V, mask, out, attT);

    dim3 g2(Ln, Bn);                              // (2048, 16)
    normalize_kernel<<<g2, 512>>>(mask, attT);
}